// round 16
// baseline (speedup 1.0000x reference)
#include <cuda_runtime.h>
#include <cuda_fp16.h>
#include <cstdint>

// B=512, T=256, NE=384, H=64
__device__ __half g_WTh[192*384];   // [n][k]  n: 0-63 Wq, 64-127 Wk, 128-191 Wv

static __device__ __forceinline__ uint32_t pkh2(float lo, float hi){
  __half2 h = __floats2half2_rn(lo, hi);
  return *reinterpret_cast<uint32_t*>(&h);
}
static __device__ __forceinline__ uint32_t hex2(uint32_t v){
  uint32_t r; asm("ex2.approx.f16x2 %0, %1;" : "=r"(r) : "r"(v)); return r;
}
static __device__ __forceinline__ uint32_t smem_u32(const void* p){
  uint32_t a;
  asm("{ .reg .u64 t; cvta.to.shared.u64 t, %1; cvt.u32.u64 %0, t; }" : "=r"(a) : "l"(p));
  return a;
}
static __device__ __forceinline__ void ldm_x4(uint32_t* r, uint32_t addr){
  asm volatile("ldmatrix.sync.aligned.m8n8.x4.shared.b16 {%0,%1,%2,%3}, [%4];"
    : "=r"(r[0]), "=r"(r[1]), "=r"(r[2]), "=r"(r[3]) : "r"(addr));
}
static __device__ __forceinline__ void mma16n8k16(float* d, const uint32_t* a, const uint32_t* b){
  asm volatile(
    "mma.sync.aligned.m16n8k16.row.col.f32.f16.f16.f32 "
    "{%0,%1,%2,%3}, {%4,%5,%6,%7}, {%8,%9}, {%0,%1,%2,%3};"
    : "+f"(d[0]), "+f"(d[1]), "+f"(d[2]), "+f"(d[3])
    : "r"(a[0]), "r"(a[1]), "r"(a[2]), "r"(a[3]), "r"(b[0]), "r"(b[1]));
}

// ---------------- W transpose + fp16 convert (R8-verified, ~5.6us) ----------------
__global__ void wt_kernel(const float* __restrict__ Wk, const float* __restrict__ Wq,
                          const float* __restrict__ Wv){
  const int n = blockIdx.x;
  const int c = n & 63;
  const float* W = (n < 64) ? Wq : (n < 128 ? Wk : Wv);
  for (int k = threadIdx.x; k < 384; k += 128)
    g_WTh[n*384 + k] = __float2half(W[k*64 + c]);
}

// ---------------- Fused QKV + flash attention: one CTA per batch, 512 threads ------
// Phase 1: QKV GEMM in two 128-row halves (R15-verified warp grid 4x4, tile 32x48,
//   ldmatrix mappings unchanged); epilogues write DIRECTLY into attn smem tiles
//   (Qsh [t][h] scaled, Ksh [t][h], Vtsh [h][t]) -- no global q/k/v round trip.
// Phase 2: attn6 (R12-verified) with aq loaded from Qsh (pitch 36 words, 4g+tig banks).
__global__ __launch_bounds__(512) void fused7(const float* __restrict__ x,
                                              float* __restrict__ out){
  extern __shared__ __half sm[];
  __half* Qsh  = sm;            // [256][72]
  __half* Ksh  = sm + 18432;    // [256][72]
  __half* Vtsh = sm + 36864;    // [72][264]  rows 64..71: all ones
  __half* Ash  = sm + 55872;    // [128][40]  GEMM A (per half)
  __half* Bsh  = sm + 60992;    // [192][40]  GEMM B
  const int b = blockIdx.x;
  const int tid = threadIdx.x, lane = tid & 31, warp = tid >> 5;
  const int g = lane >> 2, tig = lane & 3;
  const int wm = warp >> 2, wn = warp & 3;     // 4 x 4 GEMM warp grid
  const float* xb = x + (size_t)b*256*384;

  // ones rows of Vtsh (region never touched by epilogues)
  {
    const __half one = __float2half(1.f);
    for (int i = tid; i < 2112; i += 512){
      int r = i/264, c1 = i - r*264;
      Vtsh[(64 + r)*264 + c1] = one;
    }
  }

  // ldmatrix per-lane address bases (R14/R15-verified layouts)
  const int a_ro = lane & 15;
  const int a_co = (lane & 16) >> 1;
  const int b_ro = (lane & 7) | ((lane & 16) >> 1);
  const int b_co = lane & 8;
  const uint32_t a_base = smem_u32(Ash) + 2*((wm*32 + a_ro)*40 + a_co);
  const uint32_t b_base = smem_u32(Bsh) + 2*((wn*48 + b_ro)*40 + b_co);

  // prefetch mappings (R15-verified)
  const int ar[2] = { tid>>3, (tid+512)>>3 };
  const int ac = tid & 7;
  const int bn0 = tid >> 2, bn1 = (tid + 512) >> 2;   // bn1 valid for tid<256
  const int bc = tid & 3;
  const uint4* Wg = (const uint4*)g_WTh;
  const float QS = 0.18033688f;    // 0.125 * log2(e)

  #pragma unroll 1
  for (int half = 0; half < 2; half++){
    const float* xh = xb + (size_t)half*128*384;
    float C[2][6][4];
    #pragma unroll
    for (int mf = 0; mf < 2; mf++)
      #pragma unroll
      for (int nf = 0; nf < 6; nf++)
        { C[mf][nf][0]=0.f; C[mf][nf][1]=0.f; C[mf][nf][2]=0.f; C[mf][nf][3]=0.f; }

    float4 ra[2]; uint4 rb0, rb1;
    ra[0] = *(const float4*)(xh + (size_t)ar[0]*384 + ac*4);
    ra[1] = *(const float4*)(xh + (size_t)ar[1]*384 + ac*4);
    rb0 = Wg[bn0*48 + bc];
    if (tid < 256) rb1 = Wg[bn1*48 + bc];

    #pragma unroll 1
    for (int ti = 0; ti < 12; ti++){
      #pragma unroll
      for (int it = 0; it < 2; it++){
        uint2 h2 = make_uint2(pkh2(ra[it].x, ra[it].y), pkh2(ra[it].z, ra[it].w));
        *(uint2*)(Ash + ar[it]*40 + ac*4) = h2;
      }
      *(uint4*)(Bsh + bn0*40 + bc*8) = rb0;
      if (tid < 256) *(uint4*)(Bsh + bn1*40 + bc*8) = rb1;
      __syncthreads();

      if (ti < 11){
        const int kn = (ti + 1) * 32;
        ra[0] = *(const float4*)(xh + (size_t)ar[0]*384 + kn + ac*4);
        ra[1] = *(const float4*)(xh + (size_t)ar[1]*384 + kn + ac*4);
        rb0 = Wg[bn0*48 + kn/8 + bc];
        if (tid < 256) rb1 = Wg[bn1*48 + kn/8 + bc];
      }

      #pragma unroll
      for (int ks = 0; ks < 2; ks++){
        uint32_t a[2][4];
        #pragma unroll
        for (int mf = 0; mf < 2; mf++)
          ldm_x4(a[mf], a_base + mf*1280 + ks*32);
        uint32_t bf[6][2];
        #pragma unroll
        for (int p = 0; p < 3; p++){
          uint32_t t[4];
          ldm_x4(t, b_base + p*1280 + ks*32);
          bf[2*p  ][0] = t[0]; bf[2*p  ][1] = t[1];
          bf[2*p+1][0] = t[2]; bf[2*p+1][1] = t[3];
        }
        #pragma unroll
        for (int nf = 0; nf < 6; nf++)
          #pragma unroll
          for (int mf = 0; mf < 2; mf++)
            mma16n8k16(C[mf][nf], a[mf], bf[nf]);
      }
      __syncthreads();
    }

    // epilogue straight into attn smem tiles
    #pragma unroll
    for (int mf = 0; mf < 2; mf++){
      const int t = half*128 + wm*32 + mf*16 + g;   // row in batch, 0..255
      #pragma unroll
      for (int nf = 0; nf < 6; nf++){
        const int n = wn*48 + nf*8 + 2*tig;
        const int id = n >> 6, h = n & 63;
        if (id == 2){         // v -> Vtsh [h][t]
          Vtsh[(h  )*264 + t    ] = __float2half(C[mf][nf][0]);
          Vtsh[(h+1)*264 + t    ] = __float2half(C[mf][nf][1]);
          Vtsh[(h  )*264 + t + 8] = __float2half(C[mf][nf][2]);
          Vtsh[(h+1)*264 + t + 8] = __float2half(C[mf][nf][3]);
        } else if (id == 1){  // k -> Ksh [t][h]
          *(uint32_t*)(Ksh + (t  )*72 + h) = pkh2(C[mf][nf][0], C[mf][nf][1]);
          *(uint32_t*)(Ksh + (t+8)*72 + h) = pkh2(C[mf][nf][2], C[mf][nf][3]);
        } else {              // q -> Qsh [t][h], scaled
          *(uint32_t*)(Qsh + (t  )*72 + h) = pkh2(C[mf][nf][0]*QS, C[mf][nf][1]*QS);
          *(uint32_t*)(Qsh + (t+8)*72 + h) = pkh2(C[mf][nf][2]*QS, C[mf][nf][3]*QS);
        }
      }
    }
  }
  __syncthreads();   // all Q/K/V tiles in smem

  // ---------------- Phase 2: flash attention (attn6 body) ----------------
  const uint32_t* Kw = (const uint32_t*)Ksh;
  const uint32_t* Vw = (const uint32_t*)Vtsh;
  const uint32_t* Qw = (const uint32_t*)Qsh;
  const int w = warp;
  const int m0 = 16*w;

  uint32_t aq[4][4];
  #pragma unroll
  for (int ks = 0; ks < 4; ks++){
    const int ko = ks*8 + tig;
    aq[ks][0] = Qw[(m0+g  )*36 + ko    ];
    aq[ks][1] = Qw[(m0+g+8)*36 + ko    ];
    aq[ks][2] = Qw[(m0+g  )*36 + ko + 4];
    aq[ks][3] = Qw[(m0+g+8)*36 + ko + 4];
  }

  float O[9][4];
  #pragma unroll
  for (int jo = 0; jo < 9; jo++){ O[jo][0]=0.f; O[jo][1]=0.f; O[jo][2]=0.f; O[jo][3]=0.f; }
  const int cd = w >> 2;
  const int jmd = ((16*(w & 3) + 15) >> 3) + 1;   // 2,4,6,8 — live j-tiles on diagonal

  for (int c = 0; c <= cd; c++){
    const int jm = (c == cd) ? jmd : 8;
    float S[8][4];
    #pragma unroll
    for (int j = 0; j < 8; j++){ S[j][0]=0.f; S[j][1]=0.f; S[j][2]=0.f; S[j][3]=0.f; }

    #pragma unroll
    for (int ks = 0; ks < 4; ks++){
      const int ko = ks*8 + tig;
      #pragma unroll
      for (int j = 0; j < 8; j++){
        if (j < jm){
          const int kr = (c*64 + j*8 + g)*36 + ko;
          uint32_t bf[2] = { Kw[kr], Kw[kr + 4] };
          mma16n8k16(S[j], aq[ks], bf);
        }
      }
    }
    if (c == cd){   // causal mask: exp2(-100) == 0
      #pragma unroll
      for (int j = 0; j < 8; j++){
        if (j < jm){
          const int col = c*64 + j*8 + 2*tig;
          if (col     > m0+g  ) S[j][0] = -100.f;
          if (col + 1 > m0+g  ) S[j][1] = -100.f;
          if (col     > m0+g+8) S[j][2] = -100.f;
          if (col + 1 > m0+g+8) S[j][3] = -100.f;
        }
      }
    }

    #pragma unroll
    for (int kk = 0; kk < 4; kk++){
      if (2*kk < jm){
        uint32_t ap[4];
        ap[0] = hex2(pkh2(S[2*kk  ][0], S[2*kk  ][1]));
        ap[1] = hex2(pkh2(S[2*kk  ][2], S[2*kk  ][3]));
        ap[2] = hex2(pkh2(S[2*kk+1][0], S[2*kk+1][1]));
        ap[3] = hex2(pkh2(S[2*kk+1][2], S[2*kk+1][3]));
        const int tb = c*32 + kk*8 + tig;
        #pragma unroll
        for (int jo = 0; jo < 9; jo++){
          const int vr = (jo*8 + g)*132 + tb;
          uint32_t bv[2] = { Vw[vr], Vw[vr + 4] };
          mma16n8k16(O[jo], ap, bv);
        }
      }
    }
  }

  const float inv0 = 1.0f / O[8][0], inv1 = 1.0f / O[8][2];
  float* ob = out + (size_t)b*16384;
  #pragma unroll
  for (int jo = 0; jo < 8; jo++){
    *(float2*)(ob + (m0+g  )*64 + jo*8 + 2*tig) = make_float2(O[jo][0]*inv0, O[jo][1]*inv0);
    *(float2*)(ob + (m0+g+8)*64 + jo*8 + 2*tig) = make_float2(O[jo][2]*inv1, O[jo][3]*inv1);
  }
}

extern "C" void kernel_launch(void* const* d_in, const int* in_sizes, int n_in,
                              void* d_out, int out_size) {
  const float* x  = (const float*)d_in[0];
  const float* Wk = (const float*)d_in[1];
  const float* Wq = (const float*)d_in[2];
  const float* Wv = (const float*)d_in[3];
  float* out = (float*)d_out;
  (void)in_sizes; (void)n_in; (void)out_size;

  cudaFuncSetAttribute(fused7, cudaFuncAttributeMaxDynamicSharedMemorySize, 137344);

  wt_kernel<<<192, 128>>>(Wk, Wq, Wv);
  fused7<<<512, 512, 137344>>>(x, out);
}

// round 17
// speedup vs baseline: 1.4069x; 1.4069x over previous
#include <cuda_runtime.h>
#include <cuda_fp16.h>
#include <cstdint>

// B=512, T=256, NE=384, H=64
__device__ __half g_qh [512*256*64];   // [b][t][h]  (pre-scaled by H^-0.5 * log2e)
__device__ __half g_kh [512*256*64];   // [b][t][h]
__device__ __half g_vTh[512*64*256];   // [b][h][t]
__device__ __half g_WTh[192*384];      // [n][k]  n: 0-63 Wq, 64-127 Wk, 128-191 Wv

static __device__ __forceinline__ uint32_t pkh2(float lo, float hi){
  __half2 h = __floats2half2_rn(lo, hi);
  return *reinterpret_cast<uint32_t*>(&h);
}
static __device__ __forceinline__ uint32_t hex2(uint32_t v){
  uint32_t r; asm("ex2.approx.f16x2 %0, %1;" : "=r"(r) : "r"(v)); return r;
}
static __device__ __forceinline__ uint32_t smem_u32(const void* p){
  uint32_t a;
  asm("{ .reg .u64 t; cvta.to.shared.u64 t, %1; cvt.u32.u64 %0, t; }" : "=r"(a) : "l"(p));
  return a;
}
static __device__ __forceinline__ void ldm_x4(uint32_t* r, uint32_t addr){
  asm volatile("ldmatrix.sync.aligned.m8n8.x4.shared.b16 {%0,%1,%2,%3}, [%4];"
    : "=r"(r[0]), "=r"(r[1]), "=r"(r[2]), "=r"(r[3]) : "r"(addr));
}
static __device__ __forceinline__ void mma16n8k16(float* d, const uint32_t* a, const uint32_t* b){
  asm volatile(
    "mma.sync.aligned.m16n8k16.row.col.f32.f16.f16.f32 "
    "{%0,%1,%2,%3}, {%4,%5,%6,%7}, {%8,%9}, {%0,%1,%2,%3};"
    : "+f"(d[0]), "+f"(d[1]), "+f"(d[2]), "+f"(d[3])
    : "r"(a[0]), "r"(a[1]), "r"(a[2]), "r"(a[3]), "r"(b[0]), "r"(b[1]));
}

// ---------------- W transpose + fp16 convert (R8-verified, ~5.6us) ----------------
__global__ void wt_kernel(const float* __restrict__ Wk, const float* __restrict__ Wq,
                          const float* __restrict__ Wv){
  const int n = blockIdx.x;
  const int c = n & 63;
  const float* W = (n < 64) ? Wq : (n < 128 ? Wk : Wv);
  for (int k = threadIdx.x; k < 384; k += 128)
    g_WTh[n*384 + k] = __float2half(W[k*64 + c]);
}

// ---------------- QKV projection: 512 threads, 4x4 warps, k-tile 64 ----------------
// R15 structure, k-tile doubled to 64 (6 iterations, 12 syncs vs 24; 48-HMMA runs).
// Pitch 72 halves = 144B rows -> 8-row ldmatrix sets hit banks {0,16,..,112}: clean.
__global__ __launch_bounds__(512) void qkv_mma(const float* __restrict__ x){
  __shared__ __half Ash[128*72];   // [m][k] pitch 72 halves (18 KB)
  __shared__ __half Bsh[192*72];   // [n][k] pitch 72 halves (27 KB)
  const int tid = threadIdx.x, lane = tid & 31, warp = tid >> 5;
  const int g = lane >> 2, tig = lane & 3;
  const int wm = warp >> 2, wn = warp & 3;     // 4 x 4
  const int m0 = blockIdx.x * 128;

  float C[2][6][4];
  #pragma unroll
  for (int mf = 0; mf < 2; mf++)
    #pragma unroll
    for (int nf = 0; nf < 6; nf++)
      { C[mf][nf][0]=0.f; C[mf][nf][1]=0.f; C[mf][nf][2]=0.f; C[mf][nf][3]=0.f; }

  // ldmatrix per-lane address bases (fragment mappings unchanged; pitch 72)
  const int a_ro = lane & 15;
  const int a_co = (lane & 16) >> 1;
  const int b_ro = (lane & 7) | ((lane & 16) >> 1);
  const int b_co = lane & 8;
  const uint32_t a_base = smem_u32(Ash) + 2*((wm*32 + a_ro)*72 + a_co);
  const uint32_t b_base = smem_u32(Bsh) + 2*((wn*48 + b_ro)*72 + b_co);

  // prefetch: A = 2048 float4 (4 rounds), B = 1536 uint4 (3 rounds) per 64-k tile
  const int ar[4] = { tid>>4, (tid+512)>>4, (tid+1024)>>4, (tid+1536)>>4 };
  const int ac = tid & 15;
  const int bn[3] = { tid>>3, (tid+512)>>3, (tid+1024)>>3 };
  const int bc = tid & 7;
  const uint4* Wg = (const uint4*)g_WTh;

  float4 ra[4]; uint4 rb[3];
  #pragma unroll
  for (int it = 0; it < 4; it++)
    ra[it] = *(const float4*)(x + (size_t)(m0 + ar[it])*384 + ac*4);
  #pragma unroll
  for (int it = 0; it < 3; it++)
    rb[it] = Wg[bn[it]*48 + bc];

  #pragma unroll 1
  for (int ti = 0; ti < 6; ti++){
    // commit prefetched 64-k tile
    #pragma unroll
    for (int it = 0; it < 4; it++){
      uint2 h2 = make_uint2(pkh2(ra[it].x, ra[it].y), pkh2(ra[it].z, ra[it].w));
      *(uint2*)(Ash + ar[it]*72 + ac*4) = h2;
    }
    #pragma unroll
    for (int it = 0; it < 3; it++)
      *(uint4*)(Bsh + bn[it]*72 + bc*8) = rb[it];
    __syncthreads();

    if (ti < 5){   // prefetch next k-tile (flies during the MMAs)
      const int kn = (ti + 1) * 64;
      #pragma unroll
      for (int it = 0; it < 4; it++)
        ra[it] = *(const float4*)(x + (size_t)(m0 + ar[it])*384 + kn + ac*4);
      #pragma unroll
      for (int it = 0; it < 3; it++)
        rb[it] = Wg[bn[it]*48 + (ti + 1)*8 + bc];
    }

    #pragma unroll
    for (int ks = 0; ks < 4; ks++){
      uint32_t a[2][4];
      #pragma unroll
      for (int mf = 0; mf < 2; mf++)
        ldm_x4(a[mf], a_base + mf*2304 + ks*32);
      uint32_t bf[6][2];
      #pragma unroll
      for (int p = 0; p < 3; p++){
        uint32_t t[4];
        ldm_x4(t, b_base + p*2304 + ks*32);
        bf[2*p  ][0] = t[0]; bf[2*p  ][1] = t[1];
        bf[2*p+1][0] = t[2]; bf[2*p+1][1] = t[3];
      }
      #pragma unroll
      for (int nf = 0; nf < 6; nf++)
        #pragma unroll
        for (int mf = 0; mf < 2; mf++)
          mma16n8k16(C[mf][nf], a[mf], bf[nf]);
    }
    __syncthreads();
  }

  // Epilogue: q scaled by 0.125*log2(e); k [t][h]; v [b][h][t]
  const float QS = 0.18033688f;
  const int bb = m0 >> 8;
  #pragma unroll
  for (int mf = 0; mf < 2; mf++){
    const int mlo = m0 + wm*32 + mf*16 + g;
    const int t = mlo & 255;
    #pragma unroll
    for (int nf = 0; nf < 6; nf++){
      const int n = wn*48 + nf*8 + 2*tig;
      const int id = n >> 6, h = n & 63;
      if (id == 2){         // v
        __half* base = g_vTh + (size_t)bb*16384;
        base[(h  )*256 + t    ] = __float2half(C[mf][nf][0]);
        base[(h+1)*256 + t    ] = __float2half(C[mf][nf][1]);
        base[(h  )*256 + t + 8] = __float2half(C[mf][nf][2]);
        base[(h+1)*256 + t + 8] = __float2half(C[mf][nf][3]);
      } else if (id == 1){  // k
        *(uint32_t*)(g_kh + (size_t)(mlo  )*64 + h) = pkh2(C[mf][nf][0], C[mf][nf][1]);
        *(uint32_t*)(g_kh + (size_t)(mlo+8)*64 + h) = pkh2(C[mf][nf][2], C[mf][nf][3]);
      } else {              // q
        *(uint32_t*)(g_qh + (size_t)(mlo  )*64 + h) = pkh2(C[mf][nf][0]*QS, C[mf][nf][1]*QS);
        *(uint32_t*)(g_qh + (size_t)(mlo+8)*64 + h) = pkh2(C[mf][nf][2]*QS, C[mf][nf][3]*QS);
      }
    }
  }
}

// ---------------- fp16 flash attention (R12/R13-verified, 35.6us) ----------------
__global__ __launch_bounds__(512) void attn6(float* __restrict__ out){
  extern __shared__ __half smh[];
  __half* Ksh  = smh;            // [256][72]
  __half* Vtsh = smh + 256*72;   // [72][264]  rows 64..71: all ones
  const int b = blockIdx.x;
  const int tid = threadIdx.x, lane = tid & 31, w = tid >> 5;
  const int g = lane >> 2, tig = lane & 3;
  const uint32_t* Kw = (const uint32_t*)Ksh;
  const uint32_t* Vw = (const uint32_t*)Vtsh;

  {
    const uint4* Kg = (const uint4*)(g_kh  + (size_t)b*16384);
    const uint4* Vg = (const uint4*)(g_vTh + (size_t)b*16384);
    #pragma unroll
    for (int it = 0; it < 4; it++){
      int i = tid + 512*it;
      *(uint4*)(Ksh + (i>>3)*72 + (i&7)*8) = Kg[i];
      *(uint4*)(Vtsh + (i>>5)*264 + (i&31)*8) = Vg[i];
    }
    const __half one = __float2half(1.f);
    for (int i = tid; i < 2112; i += 512){
      int r = i/264, c1 = i - r*264;
      Vtsh[(64 + r)*264 + c1] = one;
    }
  }
  __syncthreads();

  const uint32_t* qp = (const uint32_t*)(g_qh + (size_t)b*16384);
  const int m0 = 16*w;

  uint32_t aq[4][4];
  #pragma unroll
  for (int ks = 0; ks < 4; ks++){
    const int ko = ks*8 + tig;
    aq[ks][0] = qp[(m0+g  )*32 + ko    ];
    aq[ks][1] = qp[(m0+g+8)*32 + ko    ];
    aq[ks][2] = qp[(m0+g  )*32 + ko + 4];
    aq[ks][3] = qp[(m0+g+8)*32 + ko + 4];
  }

  float O[9][4];
  #pragma unroll
  for (int jo = 0; jo < 9; jo++){ O[jo][0]=0.f; O[jo][1]=0.f; O[jo][2]=0.f; O[jo][3]=0.f; }
  const int cd = w >> 2;
  const int jmd = ((16*(w & 3) + 15) >> 3) + 1;   // 2,4,6,8 — live j-tiles on diagonal

  for (int c = 0; c <= cd; c++){
    const int jm = (c == cd) ? jmd : 8;
    float S[8][4];
    #pragma unroll
    for (int j = 0; j < 8; j++){ S[j][0]=0.f; S[j][1]=0.f; S[j][2]=0.f; S[j][3]=0.f; }

    #pragma unroll
    for (int ks = 0; ks < 4; ks++){
      const int ko = ks*8 + tig;
      #pragma unroll
      for (int j = 0; j < 8; j++){
        if (j < jm){
          const int kr = (c*64 + j*8 + g)*36 + ko;
          uint32_t bf[2] = { Kw[kr], Kw[kr + 4] };
          mma16n8k16(S[j], aq[ks], bf);
        }
      }
    }
    if (c == cd){   // causal mask: exp2(-100) == 0
      #pragma unroll
      for (int j = 0; j < 8; j++){
        if (j < jm){
          const int col = c*64 + j*8 + 2*tig;
          if (col     > m0+g  ) S[j][0] = -100.f;
          if (col + 1 > m0+g  ) S[j][1] = -100.f;
          if (col     > m0+g+8) S[j][2] = -100.f;
          if (col + 1 > m0+g+8) S[j][3] = -100.f;
        }
      }
    }

    #pragma unroll
    for (int kk = 0; kk < 4; kk++){
      if (2*kk < jm){
        uint32_t ap[4];
        ap[0] = hex2(pkh2(S[2*kk  ][0], S[2*kk  ][1]));
        ap[1] = hex2(pkh2(S[2*kk  ][2], S[2*kk  ][3]));
        ap[2] = hex2(pkh2(S[2*kk+1][0], S[2*kk+1][1]));
        ap[3] = hex2(pkh2(S[2*kk+1][2], S[2*kk+1][3]));
        const int tb = c*32 + kk*8 + tig;
        #pragma unroll
        for (int jo = 0; jo < 9; jo++){
          const int vr = (jo*8 + g)*132 + tb;
          uint32_t bv[2] = { Vw[vr], Vw[vr + 4] };
          mma16n8k16(O[jo], ap, bv);
        }
      }
    }
  }

  const float inv0 = 1.0f / O[8][0], inv1 = 1.0f / O[8][2];
  float* ob = out + (size_t)b*16384;
  #pragma unroll
  for (int jo = 0; jo < 8; jo++){
    *(float2*)(ob + (m0+g  )*64 + jo*8 + 2*tig) = make_float2(O[jo][0]*inv0, O[jo][1]*inv0);
    *(float2*)(ob + (m0+g+8)*64 + jo*8 + 2*tig) = make_float2(O[jo][2]*inv1, O[jo][3]*inv1);
  }
}

extern "C" void kernel_launch(void* const* d_in, const int* in_sizes, int n_in,
                              void* d_out, int out_size) {
  const float* x  = (const float*)d_in[0];
  const float* Wk = (const float*)d_in[1];
  const float* Wq = (const float*)d_in[2];
  const float* Wv = (const float*)d_in[3];
  float* out = (float*)d_out;
  (void)in_sizes; (void)n_in; (void)out_size;

  cudaFuncSetAttribute(attn6, cudaFuncAttributeMaxDynamicSharedMemorySize, 74880);

  wt_kernel<<<192, 128>>>(Wk, Wq, Wv);
  qkv_mma<<<1024, 512>>>(x);
  attn6<<<512, 512, 74880>>>(out);
}